// round 3
// baseline (speedup 1.0000x reference)
#include <cuda_runtime.h>
#include <cuda_bf16.h>

// Problem constants (fixed by the reference)
#define NNODES 50000
#define NEDGES 800000
#define NIN    128
#define NHID   256

// Scratch (allocation-free rule: __device__ globals)
__device__ float  g_deg [NNODES];
__device__ float  g_dinv[NNODES];
__device__ float4 g_agg4[NNODES * NIN / 4];   // 25.6 MB, 16B-aligned
__device__ float  g_h1  [NNODES * NHID];      // 51.2 MB
__device__ int    g_row [NEDGES];
__device__ int    g_col [NEDGES];
__device__ int    g_is64;                      // edge-index dtype flag

// ---------------------------------------------------------------------------
// Phase 0a: detect edge-index dtype (int32 vs int64).
// int64 data with values < 50000 has all-zero high words; int32 data has
// edge indices in the odd slots (virtually never all zero across 4096 pairs).
// ---------------------------------------------------------------------------
__global__ void detect_idx_kernel(const int* __restrict__ ei32) {
    __shared__ int bad;   // nonzero high word seen -> int32
    if (threadIdx.x == 0) bad = 0;
    __syncthreads();
    for (int k = threadIdx.x; k < 4096; k += blockDim.x) {
        int hi = ei32[2 * k + 1];
        int lo = ei32[2 * k];
        if (hi != 0 || (unsigned)lo >= (unsigned)NNODES) bad = 1;
    }
    __syncthreads();
    if (threadIdx.x == 0) g_is64 = bad ? 0 : 1;
}

// Phase 0b/1a fused: convert indices to int32 AND accumulate degree over col.
// g_deg must be pre-initialized to 1.0 (self-loop) by init_deg_kernel.
__global__ void convert_idx_kernel(const void* __restrict__ ei) {
    int e = blockIdx.x * blockDim.x + threadIdx.x;
    if (e >= NEDGES) return;
    int r, c;
    if (g_is64) {
        const long long* p = (const long long*)ei;
        r = (int)p[e];
        c = (int)p[NEDGES + e];
    } else {
        const int* p = (const int*)ei;
        r = p[e];
        c = p[NEDGES + e];
    }
    // defensive clamp: wrong detection -> measurable rel_err, never an IMA
    r = min(max(r, 0), NNODES - 1);
    c = min(max(c, 0), NNODES - 1);
    g_row[e] = r;
    g_col[e] = c;
    atomicAdd(&g_deg[c], 1.0f);
}

// ---------------------------------------------------------------------------
// Phase 1: degrees + normalization
// ---------------------------------------------------------------------------
__global__ void init_deg_kernel() {
    int i = blockIdx.x * blockDim.x + threadIdx.x;
    if (i < NNODES) g_deg[i] = 1.0f;   // self-loop
}

__global__ void dinv_kernel() {
    int i = blockIdx.x * blockDim.x + threadIdx.x;
    if (i < NNODES) g_dinv[i] = rsqrtf(g_deg[i]);
}

// agg[i] = dinv[i]^2 * x[i]   (self-loop contribution, also initializes agg)
__global__ void init_agg_kernel(const float* __restrict__ x) {
    int t = blockIdx.x * blockDim.x + threadIdx.x;       // one float4 per thread
    if (t >= NNODES * (NIN / 4)) return;
    int node = t >> 5;                                    // /(NIN/4)
    float s = g_dinv[node];
    s = s * s;
    float4 v = ((const float4*)x)[t];
    v.x *= s; v.y *= s; v.z *= s; v.w *= s;
    g_agg4[t] = v;
}

// ---------------------------------------------------------------------------
// Phase 2: edge scatter.  One warp per edge; 32 lanes x float4 = 128 floats.
// red.global.add.v4.f32 (sm_90+) -> 32 vector reductions per edge.
// ---------------------------------------------------------------------------
__device__ __forceinline__ void red_add_v4(float4* addr, float4 v) {
    asm volatile("red.global.add.v4.f32 [%0], {%1, %2, %3, %4};"
                 :: "l"(addr), "f"(v.x), "f"(v.y), "f"(v.z), "f"(v.w)
                 : "memory");
}

__global__ void scatter_kernel(const float* __restrict__ x) {
    int warp = (blockIdx.x * blockDim.x + threadIdx.x) >> 5;
    int lane = threadIdx.x & 31;
    if (warp >= NEDGES) return;
    int src = g_row[warp];
    int dst = g_col[warp];
    float s = g_dinv[src] * g_dinv[dst];
    float4 v = ((const float4*)(x + (size_t)src * NIN))[lane];
    v.x *= s; v.y *= s; v.z *= s; v.w *= s;
    red_add_v4(g_agg4 + (size_t)dst * (NIN / 4) + lane, v);
}

// ---------------------------------------------------------------------------
// Phase 3: SGEMM + ReLU.  C[M,N] = relu(A[M,K] @ B[K,N]).
// 128x128 block tile, BK=8, 256 threads, 8x8 microtile.
// ---------------------------------------------------------------------------
template <int BM, int BN, int BK, int TM, int TN>
__global__ __launch_bounds__(256, 2)
void sgemm_relu_kernel(const float* __restrict__ A, const float* __restrict__ B,
                       float* __restrict__ C, int M, int K, int N) {
    __shared__ float As[BK][BM];
    __shared__ float Bs[BK][BN];

    const int bm = blockIdx.x * BM;
    const int bn = blockIdx.y * BN;
    const int tid = threadIdx.x;              // 0..255

    // A tile load mapping: 128 rows x 8 k -> 1 float4 per thread
    const int a_row = tid >> 1;               // 0..127
    const int a_col = (tid & 1) * 4;          // 0 or 4
    // B tile load mapping: 8 k x 128 cols -> 1 float4 per thread
    const int b_row = tid >> 5;               // 0..7
    const int b_col = (tid & 31) * 4;         // 0..124

    const int ty = tid / 16;                  // 0..15  (row group)
    const int tx = tid % 16;                  // 0..15  (col group)

    float acc[TM][TN];
#pragma unroll
    for (int i = 0; i < TM; i++)
#pragma unroll
        for (int j = 0; j < TN; j++) acc[i][j] = 0.0f;

    for (int k0 = 0; k0 < K; k0 += BK) {
        // load A (guard M edge)
        {
            int gm = bm + a_row;
            float4 av = make_float4(0.f, 0.f, 0.f, 0.f);
            if (gm < M)
                av = *(const float4*)(A + (size_t)gm * K + k0 + a_col);
            As[a_col + 0][a_row] = av.x;
            As[a_col + 1][a_row] = av.y;
            As[a_col + 2][a_row] = av.z;
            As[a_col + 3][a_row] = av.w;
        }
        // load B (always in bounds: K % 8 == 0, N covered by grid)
        {
            float4 bv = *(const float4*)(B + (size_t)(k0 + b_row) * N + bn + b_col);
            *(float4*)&Bs[b_row][b_col] = bv;
        }
        __syncthreads();

#pragma unroll
        for (int k = 0; k < BK; k++) {
            float ar[TM], br[TN];
#pragma unroll
            for (int i = 0; i < TM; i++) ar[i] = As[k][ty * TM + i];
#pragma unroll
            for (int j = 0; j < TN; j++) br[j] = Bs[k][tx * TN + j];
#pragma unroll
            for (int i = 0; i < TM; i++)
#pragma unroll
                for (int j = 0; j < TN; j++)
                    acc[i][j] = fmaf(ar[i], br[j], acc[i][j]);
        }
        __syncthreads();
    }

    // store with ReLU, float4-vectorized
#pragma unroll
    for (int i = 0; i < TM; i++) {
        int grow = bm + ty * TM + i;
        if (grow >= M) continue;
#pragma unroll
        for (int j = 0; j < TN; j += 4) {
            float4 v;
            v.x = fmaxf(acc[i][j + 0], 0.0f);
            v.y = fmaxf(acc[i][j + 1], 0.0f);
            v.z = fmaxf(acc[i][j + 2], 0.0f);
            v.w = fmaxf(acc[i][j + 3], 0.0f);
            *(float4*)(C + (size_t)grow * N + bn + tx * TN + j) = v;
        }
    }
}

// ---------------------------------------------------------------------------
// Launch
// ---------------------------------------------------------------------------
extern "C" void kernel_launch(void* const* d_in, const int* in_sizes, int n_in,
                              void* d_out, int out_size) {
    // Identify inputs by (distinct) element counts — robust to metadata order.
    const float* x = nullptr;
    const float* W0 = nullptr;
    const float* W1 = nullptr;
    const void*  ei = nullptr;
    for (int i = 0; i < n_in; i++) {
        switch (in_sizes[i]) {
            case NNODES * NIN:   x  = (const float*)d_in[i]; break; // 6,400,000
            case NIN * NHID:     W0 = (const float*)d_in[i]; break; //    32,768
            case NHID * NHID:    W1 = (const float*)d_in[i]; break; //    65,536
            case 2 * NEDGES:     ei = d_in[i];               break; // 1,600,000
        }
    }

    float* out = (float*)d_out;

    float* agg; cudaGetSymbolAddress((void**)&agg, g_agg4);
    float* h1;  cudaGetSymbolAddress((void**)&h1,  g_h1);

    // Phase 0/1: dtype detection, deg init, fused convert+degree-count
    detect_idx_kernel<<<1, 256>>>((const int*)ei);
    init_deg_kernel<<<(NNODES + 255) / 256, 256>>>();
    convert_idx_kernel<<<(NEDGES + 255) / 256, 256>>>(ei);
    dinv_kernel<<<(NNODES + 255) / 256, 256>>>();
    init_agg_kernel<<<(NNODES * (NIN / 4) + 255) / 256, 256>>>(x);

    // Phase 2: one warp per edge
    {
        long long total_threads = (long long)NEDGES * 32;
        int blocks = (int)((total_threads + 255) / 256);
        scatter_kernel<<<blocks, 256>>>(x);
    }

    // Phase 3: GEMMs + ReLU
    {
        dim3 grid1((NNODES + 127) / 128, NHID / 128);
        sgemm_relu_kernel<128, 128, 8, 8, 8><<<grid1, 256>>>(agg, W0, h1,
                                                             NNODES, NIN, NHID);
        dim3 grid2((NNODES + 127) / 128, NHID / 128);
        sgemm_relu_kernel<128, 128, 8, 8, 8><<<grid2, 256>>>(h1, W1, out,
                                                             NNODES, NHID, NHID);
    }
}

// round 4
// speedup vs baseline: 1.8858x; 1.8858x over previous
#include <cuda_runtime.h>
#include <cuda_bf16.h>
#include <cstdint>

// Problem constants (fixed by the reference)
#define NNODES 50000
#define NEDGES 800000
#define NIN    128
#define NHID   256

// Scratch (allocation-free rule: __device__ globals)
__device__ float  g_deg [NNODES];
__device__ float  g_dinv[NNODES];
__device__ float4 g_agg4[NNODES * NIN / 4];   // 25.6 MB, 16B-aligned
__device__ float  g_h1  [NNODES * NHID];      // 51.2 MB
__device__ int    g_row [NEDGES];
__device__ int    g_col [NEDGES];
__device__ int    g_is64;                      // edge-index dtype flag

// ---------------------------------------------------------------------------
// Phase 0a: detect edge-index dtype (int32 vs int64).
// ---------------------------------------------------------------------------
__global__ void detect_idx_kernel(const int* __restrict__ ei32) {
    __shared__ int bad;   // nonzero high word seen -> int32
    if (threadIdx.x == 0) bad = 0;
    __syncthreads();
    for (int k = threadIdx.x; k < 4096; k += blockDim.x) {
        int hi = ei32[2 * k + 1];
        int lo = ei32[2 * k];
        if (hi != 0 || (unsigned)lo >= (unsigned)NNODES) bad = 1;
    }
    __syncthreads();
    if (threadIdx.x == 0) g_is64 = bad ? 0 : 1;
}

// Phase 0b/1a fused: convert indices to int32 AND accumulate degree over col.
__global__ void convert_idx_kernel(const void* __restrict__ ei) {
    int e = blockIdx.x * blockDim.x + threadIdx.x;
    if (e >= NEDGES) return;
    int r, c;
    if (g_is64) {
        const long long* p = (const long long*)ei;
        r = (int)p[e];
        c = (int)p[NEDGES + e];
    } else {
        const int* p = (const int*)ei;
        r = p[e];
        c = p[NEDGES + e];
    }
    r = min(max(r, 0), NNODES - 1);
    c = min(max(c, 0), NNODES - 1);
    g_row[e] = r;
    g_col[e] = c;
    atomicAdd(&g_deg[c], 1.0f);
}

// ---------------------------------------------------------------------------
// Phase 1: degrees + normalization
// ---------------------------------------------------------------------------
__global__ void init_deg_kernel() {
    int i = blockIdx.x * blockDim.x + threadIdx.x;
    if (i < NNODES) g_deg[i] = 1.0f;   // self-loop
}

__global__ void dinv_kernel() {
    int i = blockIdx.x * blockDim.x + threadIdx.x;
    if (i < NNODES) g_dinv[i] = rsqrtf(g_deg[i]);
}

// agg[i] = dinv[i]^2 * x[i]   (self-loop contribution, also initializes agg)
__global__ void init_agg_kernel(const float* __restrict__ x) {
    int t = blockIdx.x * blockDim.x + threadIdx.x;       // one float4 per thread
    if (t >= NNODES * (NIN / 4)) return;
    int node = t >> 5;                                    // /(NIN/4)
    float s = g_dinv[node];
    s = s * s;
    float4 v = ((const float4*)x)[t];
    v.x *= s; v.y *= s; v.z *= s; v.w *= s;
    g_agg4[t] = v;
}

// ---------------------------------------------------------------------------
// Phase 2: edge scatter.  One warp per edge; 32 lanes x float4 = 128 floats.
// ---------------------------------------------------------------------------
__device__ __forceinline__ void red_add_v4(float4* addr, float4 v) {
    asm volatile("red.global.add.v4.f32 [%0], {%1, %2, %3, %4};"
                 :: "l"(addr), "f"(v.x), "f"(v.y), "f"(v.z), "f"(v.w)
                 : "memory");
}

__global__ void scatter_kernel(const float* __restrict__ x) {
    int warp = (blockIdx.x * blockDim.x + threadIdx.x) >> 5;
    int lane = threadIdx.x & 31;
    if (warp >= NEDGES) return;
    int src = g_row[warp];
    int dst = g_col[warp];
    float s = g_dinv[src] * g_dinv[dst];
    float4 v = ((const float4*)(x + (size_t)src * NIN))[lane];
    v.x *= s; v.y *= s; v.z *= s; v.w *= s;
    red_add_v4(g_agg4 + (size_t)dst * (NIN / 4) + lane, v);
}

// ---------------------------------------------------------------------------
// Phase 3: TF32 tensor-core GEMM + ReLU.  C[M,N] = relu(A[M,K] @ B[K,N]).
// 128x128 block tile, BK=32, 256 threads (2x4 warps), warp tile 64x32,
// mma.sync.aligned.m16n8k8.row.col.f32.tf32.tf32.f32.
// ---------------------------------------------------------------------------
__device__ __forceinline__ uint32_t f32_to_tf32(float f) {
    uint32_t u;
    asm("cvt.rna.tf32.f32 %0, %1;" : "=r"(u) : "f"(f));
    return u;
}

__device__ __forceinline__ void mma_tf32(float* c, const uint32_t* a,
                                         const uint32_t* b) {
    asm volatile(
        "mma.sync.aligned.m16n8k8.row.col.f32.tf32.tf32.f32 "
        "{%0,%1,%2,%3}, {%4,%5,%6,%7}, {%8,%9}, {%0,%1,%2,%3};"
        : "+f"(c[0]), "+f"(c[1]), "+f"(c[2]), "+f"(c[3])
        : "r"(a[0]), "r"(a[1]), "r"(a[2]), "r"(a[3]), "r"(b[0]), "r"(b[1]));
}

// Smem pads: A +4 (frag-read addr mod32 = r*4+k, conflict-free),
//            B +8 (frag-read addr mod32 = k*8+n, conflict-free).
#define APAD 36
#define BPAD 136

__global__ __launch_bounds__(256, 2)
void gemm_tf32_relu_kernel(const float* __restrict__ A,
                           const float* __restrict__ B,
                           float* __restrict__ C, int M, int K, int N) {
    __shared__ uint32_t As[128 * APAD];   // [row][k]
    __shared__ uint32_t Bs[32 * BPAD];    // [k][col]

    const int tid  = threadIdx.x;
    const int lane = tid & 31;
    const int wid  = tid >> 5;
    const int wm   = (wid & 1) * 64;      // warp row offset in tile
    const int wn   = (wid >> 1) * 32;     // warp col offset in tile
    const int gid  = lane >> 2;           // groupID (0..7)
    const int tig  = lane & 3;            // thread-in-group (0..3)

    const int bm = blockIdx.x * 128;
    const int bn = blockIdx.y * 128;

    float acc[4][4][4];                   // [mt][nt][frag]
#pragma unroll
    for (int i = 0; i < 4; i++)
#pragma unroll
        for (int j = 0; j < 4; j++)
#pragma unroll
            for (int f = 0; f < 4; f++) acc[i][j][f] = 0.0f;

    for (int k0 = 0; k0 < K; k0 += 32) {
        // ---- fill A smem: 128 rows x 32 k, tf32-converted ----
#pragma unroll
        for (int i = 0; i < 4; i++) {
            int v   = i * 256 + tid;      // 0..1023 float4 slots
            int row = v >> 3;             // 8 float4 per row
            int col = (v & 7) * 4;
            float4 av = make_float4(0.f, 0.f, 0.f, 0.f);
            int gm = bm + row;
            if (gm < M)
                av = *(const float4*)(A + (size_t)gm * K + k0 + col);
            uint32_t* dst = &As[row * APAD + col];
            uint4 u;
            u.x = f32_to_tf32(av.x); u.y = f32_to_tf32(av.y);
            u.z = f32_to_tf32(av.z); u.w = f32_to_tf32(av.w);
            *(uint4*)dst = u;
        }
        // ---- fill B smem: 32 k x 128 cols, tf32-converted ----
#pragma unroll
        for (int i = 0; i < 4; i++) {
            int v   = i * 256 + tid;
            int row = v >> 5;             // 32 float4 per row
            int col = (v & 31) * 4;
            float4 bv = *(const float4*)(B + (size_t)(k0 + row) * N + bn + col);
            uint32_t* dst = &Bs[row * BPAD + col];
            uint4 u;
            u.x = f32_to_tf32(bv.x); u.y = f32_to_tf32(bv.y);
            u.z = f32_to_tf32(bv.z); u.w = f32_to_tf32(bv.w);
            *(uint4*)dst = u;
        }
        __syncthreads();

#pragma unroll
        for (int ks = 0; ks < 4; ks++) {
            const int kk = ks * 8;
            uint32_t a[4][4], b[4][2];
#pragma unroll
            for (int mt = 0; mt < 4; mt++) {
                int r = wm + mt * 16 + gid;
                a[mt][0] = As[(r    ) * APAD + kk + tig    ];
                a[mt][1] = As[(r + 8) * APAD + kk + tig    ];
                a[mt][2] = As[(r    ) * APAD + kk + tig + 4];
                a[mt][3] = As[(r + 8) * APAD + kk + tig + 4];
            }
#pragma unroll
            for (int nt = 0; nt < 4; nt++) {
                int n = wn + nt * 8 + gid;
                b[nt][0] = Bs[(kk + tig    ) * BPAD + n];
                b[nt][1] = Bs[(kk + tig + 4) * BPAD + n];
            }
#pragma unroll
            for (int mt = 0; mt < 4; mt++)
#pragma unroll
                for (int nt = 0; nt < 4; nt++)
                    mma_tf32(acc[mt][nt], a[mt], b[nt]);
        }
        __syncthreads();
    }

    // ---- epilogue: ReLU + store (float2 per fragment half) ----
#pragma unroll
    for (int mt = 0; mt < 4; mt++) {
        int r0 = bm + wm + mt * 16 + gid;
        int r1 = r0 + 8;
#pragma unroll
        for (int nt = 0; nt < 4; nt++) {
            int cc = bn + wn + nt * 8 + tig * 2;
            if (r0 < M) {
                float2 v0;
                v0.x = fmaxf(acc[mt][nt][0], 0.0f);
                v0.y = fmaxf(acc[mt][nt][1], 0.0f);
                *(float2*)(C + (size_t)r0 * N + cc) = v0;
            }
            if (r1 < M) {
                float2 v1;
                v1.x = fmaxf(acc[mt][nt][2], 0.0f);
                v1.y = fmaxf(acc[mt][nt][3], 0.0f);
                *(float2*)(C + (size_t)r1 * N + cc) = v1;
            }
        }
    }
}

// ---------------------------------------------------------------------------
// Launch
// ---------------------------------------------------------------------------
extern "C" void kernel_launch(void* const* d_in, const int* in_sizes, int n_in,
                              void* d_out, int out_size) {
    const float* x = nullptr;
    const float* W0 = nullptr;
    const float* W1 = nullptr;
    const void*  ei = nullptr;
    for (int i = 0; i < n_in; i++) {
        switch (in_sizes[i]) {
            case NNODES * NIN:   x  = (const float*)d_in[i]; break; // 6,400,000
            case NIN * NHID:     W0 = (const float*)d_in[i]; break; //    32,768
            case NHID * NHID:    W1 = (const float*)d_in[i]; break; //    65,536
            case 2 * NEDGES:     ei = d_in[i];               break; // 1,600,000
        }
    }

    float* out = (float*)d_out;

    float* agg; cudaGetSymbolAddress((void**)&agg, g_agg4);
    float* h1;  cudaGetSymbolAddress((void**)&h1,  g_h1);

    // Phase 0/1: dtype detection, deg init, fused convert+degree-count
    detect_idx_kernel<<<1, 256>>>((const int*)ei);
    init_deg_kernel<<<(NNODES + 255) / 256, 256>>>();
    convert_idx_kernel<<<(NEDGES + 255) / 256, 256>>>(ei);
    dinv_kernel<<<(NNODES + 255) / 256, 256>>>();
    init_agg_kernel<<<(NNODES * (NIN / 4) + 255) / 256, 256>>>(x);

    // Phase 2: one warp per edge
    {
        long long total_threads = (long long)NEDGES * 32;
        int blocks = (int)((total_threads + 255) / 256);
        scatter_kernel<<<blocks, 256>>>(x);
    }

    // Phase 3: TF32 tensor-core GEMMs + ReLU
    {
        dim3 grid1((NNODES + 127) / 128, NHID / 128);
        gemm_tf32_relu_kernel<<<grid1, 256>>>(agg, W0, h1, NNODES, NIN, NHID);
        dim3 grid2((NNODES + 127) / 128, NHID / 128);
        gemm_tf32_relu_kernel<<<grid2, 256>>>(h1, W1, out, NNODES, NHID, NHID);
    }
}

// round 5
// speedup vs baseline: 2.3545x; 1.2485x over previous
#include <cuda_runtime.h>
#include <cuda_bf16.h>
#include <cstdint>

// Problem constants (fixed by the reference)
#define NNODES 50000
#define NEDGES 800000
#define NIN    128
#define NHID   256
#define NB_SCAN ((NNODES + 255) / 256)   // 196

// Scratch (allocation-free rule: __device__ globals)
__device__ float  g_dinv[NNODES];
__device__ float4 g_agg4[NNODES * NIN / 4];   // 25.6 MB, 16B-aligned
__device__ float  g_h1  [NNODES * NHID];      // 51.2 MB
__device__ int    g_row [NEDGES];
__device__ int    g_col [NEDGES];
__device__ int    g_cnt [NNODES];              // incoming-edge histogram
__device__ int    g_ptr [NNODES];              // CSR row pointers (exclusive)
__device__ int    g_cur [NNODES];              // fill cursors
__device__ int    g_bsum[NB_SCAN];
__device__ int    g_boff[NB_SCAN];
__device__ int    g_esrc[NEDGES];              // CSR: source per slot
__device__ int    g_is64;                      // edge-index dtype flag

// ---------------------------------------------------------------------------
// Phase 0a: detect edge-index dtype (int32 vs int64).
// ---------------------------------------------------------------------------
__global__ void detect_idx_kernel(const int* __restrict__ ei32) {
    __shared__ int bad;
    if (threadIdx.x == 0) bad = 0;
    __syncthreads();
    for (int k = threadIdx.x; k < 4096; k += blockDim.x) {
        int hi = ei32[2 * k + 1];
        int lo = ei32[2 * k];
        if (hi != 0 || (unsigned)lo >= (unsigned)NNODES) bad = 1;
    }
    __syncthreads();
    if (threadIdx.x == 0) g_is64 = bad ? 0 : 1;
}

__global__ void zero_cnt_kernel() {
    int i = blockIdx.x * blockDim.x + threadIdx.x;
    if (i < NNODES) g_cnt[i] = 0;
}

// Phase 0b: convert indices to int32 AND histogram destinations.
__global__ void convert_idx_kernel(const void* __restrict__ ei) {
    int e = blockIdx.x * blockDim.x + threadIdx.x;
    if (e >= NEDGES) return;
    int r, c;
    if (g_is64) {
        const long long* p = (const long long*)ei;
        r = (int)p[e];
        c = (int)p[NEDGES + e];
    } else {
        const int* p = (const int*)ei;
        r = p[e];
        c = p[NEDGES + e];
    }
    r = min(max(r, 0), NNODES - 1);   // defensive: rel_err, never IMA
    c = min(max(c, 0), NNODES - 1);
    g_row[e] = r;
    g_col[e] = c;
    atomicAdd(&g_cnt[c], 1);
}

// dinv = rsqrt(1 + incoming_count)   (self-loop included)
__global__ void dinv_kernel() {
    int i = blockIdx.x * blockDim.x + threadIdx.x;
    if (i < NNODES) g_dinv[i] = rsqrtf(1.0f + (float)g_cnt[i]);
}

// ---------------------------------------------------------------------------
// Prefix sum over g_cnt -> g_ptr (3 kernels)
// ---------------------------------------------------------------------------
__global__ void scan1_kernel() {
    __shared__ int sh[256];
    int i = blockIdx.x * 256 + threadIdx.x;
    int v = (i < NNODES) ? g_cnt[i] : 0;
    sh[threadIdx.x] = v;
    __syncthreads();
#pragma unroll
    for (int off = 1; off < 256; off <<= 1) {
        int t = (threadIdx.x >= off) ? sh[threadIdx.x - off] : 0;
        __syncthreads();
        sh[threadIdx.x] += t;
        __syncthreads();
    }
    int incl = sh[threadIdx.x];
    if (i < NNODES) g_ptr[i] = incl - v;              // block-local exclusive
    if (threadIdx.x == 255) g_bsum[blockIdx.x] = incl;
}

__global__ void scan2_kernel() {
    __shared__ int sh[256];
    int v = (threadIdx.x < NB_SCAN) ? g_bsum[threadIdx.x] : 0;
    sh[threadIdx.x] = v;
    __syncthreads();
#pragma unroll
    for (int off = 1; off < 256; off <<= 1) {
        int t = (threadIdx.x >= off) ? sh[threadIdx.x - off] : 0;
        __syncthreads();
        sh[threadIdx.x] += t;
        __syncthreads();
    }
    if (threadIdx.x < NB_SCAN) g_boff[threadIdx.x] = sh[threadIdx.x] - v;
}

__global__ void scan3_kernel() {
    int i = blockIdx.x * blockDim.x + threadIdx.x;
    if (i >= NNODES) return;
    int p = g_ptr[i] + g_boff[i >> 8];
    g_ptr[i] = p;
    g_cur[i] = p;
}

// Fill CSR: slot = cursor++ per destination; store source.
__global__ void fill_csr_kernel() {
    int e = blockIdx.x * blockDim.x + threadIdx.x;
    if (e >= NEDGES) return;
    int c = g_col[e];
    int pos = atomicAdd(&g_cur[c], 1);
    g_esrc[pos] = g_row[e];
}

// ---------------------------------------------------------------------------
// Phase 2: CSR gather.  One warp per destination node; lane owns a float4
// slice (128 floats / 32 lanes).  out = dinv[i]*(dinv[i]*x[i] + sum dinv[j]x[j])
// ---------------------------------------------------------------------------
__global__ __launch_bounds__(256)
void gather_kernel(const float4* __restrict__ x4) {
    int warp = (blockIdx.x * blockDim.x + threadIdx.x) >> 5;
    int lane = threadIdx.x & 31;
    if (warp >= NNODES) return;

    const int beg = g_ptr[warp];
    const int cnt = g_cnt[warp];
    const float di = g_dinv[warp];

    // self-loop contribution: di * x[i]  (outer di applied at the end)
    float4 acc = x4[(size_t)warp * 32 + lane];
    acc.x *= di; acc.y *= di; acc.z *= di; acc.w *= di;

    int base = 0;
    // full 32-edge chunks, unrolled for MLP
    for (; base + 32 <= cnt; base += 32) {
        int   s = g_esrc[beg + base + lane];
        float w = g_dinv[s];
#pragma unroll
        for (int j = 0; j < 32; j++) {
            int   ss = __shfl_sync(0xffffffffu, s, j);
            float ww = __shfl_sync(0xffffffffu, w, j);
            float4 v = x4[(size_t)ss * 32 + lane];
            acc.x = fmaf(ww, v.x, acc.x);
            acc.y = fmaf(ww, v.y, acc.y);
            acc.z = fmaf(ww, v.z, acc.z);
            acc.w = fmaf(ww, v.w, acc.w);
        }
    }
    // tail
    {
        int rem = cnt - base;
        int   s = 0; float w = 0.0f;
        if (lane < rem) {
            s = g_esrc[beg + base + lane];
            w = g_dinv[s];
        }
        for (int j = 0; j < rem; j++) {
            int   ss = __shfl_sync(0xffffffffu, s, j);
            float ww = __shfl_sync(0xffffffffu, w, j);
            float4 v = x4[(size_t)ss * 32 + lane];
            acc.x = fmaf(ww, v.x, acc.x);
            acc.y = fmaf(ww, v.y, acc.y);
            acc.z = fmaf(ww, v.z, acc.z);
            acc.w = fmaf(ww, v.w, acc.w);
        }
    }

    acc.x *= di; acc.y *= di; acc.z *= di; acc.w *= di;
    g_agg4[(size_t)warp * 32 + lane] = acc;
}

// ---------------------------------------------------------------------------
// Phase 3: TF32 tensor-core GEMM + ReLU (unchanged from Round 4).
// ---------------------------------------------------------------------------
__device__ __forceinline__ uint32_t f32_to_tf32(float f) {
    uint32_t u;
    asm("cvt.rna.tf32.f32 %0, %1;" : "=r"(u) : "f"(f));
    return u;
}

__device__ __forceinline__ void mma_tf32(float* c, const uint32_t* a,
                                         const uint32_t* b) {
    asm volatile(
        "mma.sync.aligned.m16n8k8.row.col.f32.tf32.tf32.f32 "
        "{%0,%1,%2,%3}, {%4,%5,%6,%7}, {%8,%9}, {%0,%1,%2,%3};"
        : "+f"(c[0]), "+f"(c[1]), "+f"(c[2]), "+f"(c[3])
        : "r"(a[0]), "r"(a[1]), "r"(a[2]), "r"(a[3]), "r"(b[0]), "r"(b[1]));
}

#define APAD 36
#define BPAD 136

__global__ __launch_bounds__(256, 2)
void gemm_tf32_relu_kernel(const float* __restrict__ A,
                           const float* __restrict__ B,
                           float* __restrict__ C, int M, int K, int N) {
    __shared__ uint32_t As[128 * APAD];   // [row][k]
    __shared__ uint32_t Bs[32 * BPAD];    // [k][col]

    const int tid  = threadIdx.x;
    const int lane = tid & 31;
    const int wid  = tid >> 5;
    const int wm   = (wid & 1) * 64;
    const int wn   = (wid >> 1) * 32;
    const int gid  = lane >> 2;
    const int tig  = lane & 3;

    const int bm = blockIdx.x * 128;
    const int bn = blockIdx.y * 128;

    float acc[4][4][4];
#pragma unroll
    for (int i = 0; i < 4; i++)
#pragma unroll
        for (int j = 0; j < 4; j++)
#pragma unroll
            for (int f = 0; f < 4; f++) acc[i][j][f] = 0.0f;

    for (int k0 = 0; k0 < K; k0 += 32) {
#pragma unroll
        for (int i = 0; i < 4; i++) {
            int v   = i * 256 + tid;
            int row = v >> 3;
            int col = (v & 7) * 4;
            float4 av = make_float4(0.f, 0.f, 0.f, 0.f);
            int gm = bm + row;
            if (gm < M)
                av = *(const float4*)(A + (size_t)gm * K + k0 + col);
            uint32_t* dst = &As[row * APAD + col];
            uint4 u;
            u.x = f32_to_tf32(av.x); u.y = f32_to_tf32(av.y);
            u.z = f32_to_tf32(av.z); u.w = f32_to_tf32(av.w);
            *(uint4*)dst = u;
        }
#pragma unroll
        for (int i = 0; i < 4; i++) {
            int v   = i * 256 + tid;
            int row = v >> 5;
            int col = (v & 31) * 4;
            float4 bv = *(const float4*)(B + (size_t)(k0 + row) * N + bn + col);
            uint32_t* dst = &Bs[row * BPAD + col];
            uint4 u;
            u.x = f32_to_tf32(bv.x); u.y = f32_to_tf32(bv.y);
            u.z = f32_to_tf32(bv.z); u.w = f32_to_tf32(bv.w);
            *(uint4*)dst = u;
        }
        __syncthreads();

#pragma unroll
        for (int ks = 0; ks < 4; ks++) {
            const int kk = ks * 8;
            uint32_t a[4][4], b[4][2];
#pragma unroll
            for (int mt = 0; mt < 4; mt++) {
                int r = wm + mt * 16 + gid;
                a[mt][0] = As[(r    ) * APAD + kk + tig    ];
                a[mt][1] = As[(r + 8) * APAD + kk + tig    ];
                a[mt][2] = As[(r    ) * APAD + kk + tig + 4];
                a[mt][3] = As[(r + 8) * APAD + kk + tig + 4];
            }
#pragma unroll
            for (int nt = 0; nt < 4; nt++) {
                int n = wn + nt * 8 + gid;
                b[nt][0] = Bs[(kk + tig    ) * BPAD + n];
                b[nt][1] = Bs[(kk + tig + 4) * BPAD + n];
            }
#pragma unroll
            for (int mt = 0; mt < 4; mt++)
#pragma unroll
                for (int nt = 0; nt < 4; nt++)
                    mma_tf32(acc[mt][nt], a[mt], b[nt]);
        }
        __syncthreads();
    }

#pragma unroll
    for (int mt = 0; mt < 4; mt++) {
        int r0 = bm + wm + mt * 16 + gid;
        int r1 = r0 + 8;
#pragma unroll
        for (int nt = 0; nt < 4; nt++) {
            int cc = bn + wn + nt * 8 + tig * 2;
            if (r0 < M) {
                float2 v0;
                v0.x = fmaxf(acc[mt][nt][0], 0.0f);
                v0.y = fmaxf(acc[mt][nt][1], 0.0f);
                *(float2*)(C + (size_t)r0 * N + cc) = v0;
            }
            if (r1 < M) {
                float2 v1;
                v1.x = fmaxf(acc[mt][nt][2], 0.0f);
                v1.y = fmaxf(acc[mt][nt][3], 0.0f);
                *(float2*)(C + (size_t)r1 * N + cc) = v1;
            }
        }
    }
}

// ---------------------------------------------------------------------------
// Launch
// ---------------------------------------------------------------------------
extern "C" void kernel_launch(void* const* d_in, const int* in_sizes, int n_in,
                              void* d_out, int out_size) {
    const float* x = nullptr;
    const float* W0 = nullptr;
    const float* W1 = nullptr;
    const void*  ei = nullptr;
    for (int i = 0; i < n_in; i++) {
        switch (in_sizes[i]) {
            case NNODES * NIN:   x  = (const float*)d_in[i]; break; // 6,400,000
            case NIN * NHID:     W0 = (const float*)d_in[i]; break; //    32,768
            case NHID * NHID:    W1 = (const float*)d_in[i]; break; //    65,536
            case 2 * NEDGES:     ei = d_in[i];               break; // 1,600,000
        }
    }

    float* out = (float*)d_out;

    float* agg; cudaGetSymbolAddress((void**)&agg, g_agg4);
    float* h1;  cudaGetSymbolAddress((void**)&h1,  g_h1);

    const int NBn = (NNODES + 255) / 256;
    const int NBe = (NEDGES + 255) / 256;

    // Phase 0/1: dtype detect, histogram, dinv, CSR build
    detect_idx_kernel<<<1, 256>>>((const int*)ei);
    zero_cnt_kernel<<<NBn, 256>>>();
    convert_idx_kernel<<<NBe, 256>>>(ei);
    dinv_kernel<<<NBn, 256>>>();
    scan1_kernel<<<NB_SCAN, 256>>>();
    scan2_kernel<<<1, 256>>>();
    scan3_kernel<<<NBn, 256>>>();
    fill_csr_kernel<<<NBe, 256>>>();

    // Phase 2: CSR gather (one warp per node), self-loop fused
    {
        int blocks = (NNODES * 32 + 255) / 256;
        gather_kernel<<<blocks, 256>>>((const float4*)x);
    }

    // Phase 3: TF32 tensor-core GEMMs + ReLU
    {
        dim3 grid1((NNODES + 127) / 128, NHID / 128);
        gemm_tf32_relu_kernel<<<grid1, 256>>>(agg, W0, h1, NNODES, NIN, NHID);
        dim3 grid2((NNODES + 127) / 128, NHID / 128);
        gemm_tf32_relu_kernel<<<grid2, 256>>>(h1, W1, out, NNODES, NHID, NHID);
    }
}

// round 8
// speedup vs baseline: 2.3585x; 1.0017x over previous
#include <cuda_runtime.h>
#include <cuda_bf16.h>
#include <cstdint>

// Problem constants (fixed by the reference)
#define NNODES 50000
#define NEDGES 800000
#define NIN    128
#define NHID   256
#define NB_SCAN ((NNODES + 255) / 256)   // 196

// Scratch (allocation-free rule: __device__ globals)
__device__ float  g_dinv[NNODES];
__device__ float4 g_agg4[NNODES * NIN / 4];   // 25.6 MB, 16B-aligned
__device__ float  g_h1  [NNODES * NHID];      // 51.2 MB
__device__ int    g_row [NEDGES];
__device__ int    g_col [NEDGES];
__device__ int    g_cnt [NNODES];              // incoming-edge histogram
__device__ int    g_ptr [NNODES];              // CSR row pointers (exclusive)
__device__ int    g_cur [NNODES];              // fill cursors
__device__ int    g_bsum[NB_SCAN];
__device__ int    g_esrc[NEDGES];              // CSR: source per slot
__device__ int    g_is64;                      // edge-index dtype flag

// ---------------------------------------------------------------------------
// Fused: zero histogram + dtype detection (block 0 detects int32 vs int64).
// ---------------------------------------------------------------------------
__global__ void zero_detect_kernel(const int* __restrict__ ei32) {
    int i = blockIdx.x * 256 + threadIdx.x;
    if (i < NNODES) g_cnt[i] = 0;
    if (blockIdx.x == 0) {
        __shared__ int bad;
        if (threadIdx.x == 0) bad = 0;
        __syncthreads();
        for (int k = threadIdx.x; k < 4096; k += 256) {
            int hi = ei32[2 * k + 1];
            int lo = ei32[2 * k];
            if (hi != 0 || (unsigned)lo >= (unsigned)NNODES) bad = 1;
        }
        __syncthreads();
        if (threadIdx.x == 0) g_is64 = bad ? 0 : 1;
    }
}

// Convert indices to int32 AND histogram destinations.
__global__ void convert_idx_kernel(const void* __restrict__ ei) {
    int e = blockIdx.x * blockDim.x + threadIdx.x;
    if (e >= NEDGES) return;
    int r, c;
    if (g_is64) {
        const long long* p = (const long long*)ei;
        r = (int)p[e];
        c = (int)p[NEDGES + e];
    } else {
        const int* p = (const int*)ei;
        r = p[e];
        c = p[NEDGES + e];
    }
    r = min(max(r, 0), NNODES - 1);   // defensive: rel_err, never IMA
    c = min(max(c, 0), NNODES - 1);
    g_row[e] = r;
    g_col[e] = c;
    atomicAdd(&g_cnt[c], 1);
}

// ---------------------------------------------------------------------------
// Fused scan stage 1 + dinv: block-local exclusive scan of g_cnt,
// plus dinv[i] = rsqrt(1 + cnt[i]).
// ---------------------------------------------------------------------------
__global__ void scan1_dinv_kernel() {
    __shared__ int sh[256];
    int i = blockIdx.x * 256 + threadIdx.x;
    int v = (i < NNODES) ? g_cnt[i] : 0;
    if (i < NNODES) g_dinv[i] = rsqrtf(1.0f + (float)v);
    sh[threadIdx.x] = v;
    __syncthreads();
#pragma unroll
    for (int off = 1; off < 256; off <<= 1) {
        int t = (threadIdx.x >= off) ? sh[threadIdx.x - off] : 0;
        __syncthreads();
        sh[threadIdx.x] += t;
        __syncthreads();
    }
    int incl = sh[threadIdx.x];
    if (i < NNODES) g_ptr[i] = incl - v;              // block-local exclusive
    if (threadIdx.x == 255) g_bsum[blockIdx.x] = incl;
}

// Fused scan stages 2+3: every block redundantly scans the 196 block sums
// in smem, picks its own exclusive offset, applies it.
__global__ void scan23_kernel() {
    __shared__ int sh[256];
    __shared__ int excl;
    int t = threadIdx.x;
    int v = (t < NB_SCAN) ? g_bsum[t] : 0;
    sh[t] = v;
    __syncthreads();
#pragma unroll
    for (int off = 1; off < 256; off <<= 1) {
        int u = (t >= off) ? sh[t - off] : 0;
        __syncthreads();
        sh[t] += u;
        __syncthreads();
    }
    if (t == blockIdx.x) excl = sh[t] - v;
    __syncthreads();
    int i = blockIdx.x * 256 + t;
    if (i < NNODES) {
        int p = g_ptr[i] + excl;
        g_ptr[i] = p;
        g_cur[i] = p;
    }
}

// Fill CSR: slot = cursor++ per destination; store source.
__global__ void fill_csr_kernel() {
    int e = blockIdx.x * blockDim.x + threadIdx.x;
    if (e >= NEDGES) return;
    int c = g_col[e];
    int pos = atomicAdd(&g_cur[c], 1);
    g_esrc[pos] = g_row[e];
}

// ---------------------------------------------------------------------------
// Phase 2: CSR gather.  One warp per destination node; lane owns a float4
// slice.  out = dinv[i]*(dinv[i]*x[i] + sum dinv[j]*x[j])
// ---------------------------------------------------------------------------
__global__ __launch_bounds__(256)
void gather_kernel(const float4* __restrict__ x4) {
    int warp = (blockIdx.x * blockDim.x + threadIdx.x) >> 5;
    int lane = threadIdx.x & 31;
    if (warp >= NNODES) return;

    const int beg = g_ptr[warp];
    const int cnt = g_cnt[warp];
    const float di = g_dinv[warp];

    float4 acc = x4[(size_t)warp * 32 + lane];
    acc.x *= di; acc.y *= di; acc.z *= di; acc.w *= di;

    int base = 0;
    for (; base + 32 <= cnt; base += 32) {
        int   s = g_esrc[beg + base + lane];
        float w = g_dinv[s];
#pragma unroll
        for (int j = 0; j < 32; j++) {
            int   ss = __shfl_sync(0xffffffffu, s, j);
            float ww = __shfl_sync(0xffffffffu, w, j);
            float4 v = x4[(size_t)ss * 32 + lane];
            acc.x = fmaf(ww, v.x, acc.x);
            acc.y = fmaf(ww, v.y, acc.y);
            acc.z = fmaf(ww, v.z, acc.z);
            acc.w = fmaf(ww, v.w, acc.w);
        }
    }
    {
        int rem = cnt - base;
        int   s = 0; float w = 0.0f;
        if (lane < rem) {
            s = g_esrc[beg + base + lane];
            w = g_dinv[s];
        }
        for (int j = 0; j < rem; j++) {
            int   ss = __shfl_sync(0xffffffffu, s, j);
            float ww = __shfl_sync(0xffffffffu, w, j);
            float4 v = x4[(size_t)ss * 32 + lane];
            acc.x = fmaf(ww, v.x, acc.x);
            acc.y = fmaf(ww, v.y, acc.y);
            acc.z = fmaf(ww, v.z, acc.z);
            acc.w = fmaf(ww, v.w, acc.w);
        }
    }

    acc.x *= di; acc.y *= di; acc.z *= di; acc.w *= di;
    g_agg4[(size_t)warp * 32 + lane] = acc;
}

// ---------------------------------------------------------------------------
// Phase 3: TF32 tensor-core GEMM + ReLU (proven Round-4/5 version).
// 128x128 block tile, BK=32, 256 threads (2x4 warps), warp tile 64x32,
// mma.sync.aligned.m16n8k8.row.col.f32.tf32.tf32.f32.
// ---------------------------------------------------------------------------
__device__ __forceinline__ uint32_t f32_to_tf32(float f) {
    uint32_t u;
    asm("cvt.rna.tf32.f32 %0, %1;" : "=r"(u) : "f"(f));
    return u;
}

__device__ __forceinline__ void mma_tf32(float* c, const uint32_t* a,
                                         const uint32_t* b) {
    asm volatile(
        "mma.sync.aligned.m16n8k8.row.col.f32.tf32.tf32.f32 "
        "{%0,%1,%2,%3}, {%4,%5,%6,%7}, {%8,%9}, {%0,%1,%2,%3};"
        : "+f"(c[0]), "+f"(c[1]), "+f"(c[2]), "+f"(c[3])
        : "r"(a[0]), "r"(a[1]), "r"(a[2]), "r"(a[3]), "r"(b[0]), "r"(b[1]));
}

#define APAD 36
#define BPAD 136

__global__ __launch_bounds__(256, 2)
void gemm_tf32_relu_kernel(const float* __restrict__ A,
                           const float* __restrict__ B,
                           float* __restrict__ C, int M, int K, int N) {
    __shared__ uint32_t As[128 * APAD];   // [row][k]
    __shared__ uint32_t Bs[32 * BPAD];    // [k][col]

    const int tid  = threadIdx.x;
    const int lane = tid & 31;
    const int wid  = tid >> 5;
    const int wm   = (wid & 1) * 64;
    const int wn   = (wid >> 1) * 32;
    const int gid  = lane >> 2;
    const int tig  = lane & 3;

    const int bm = blockIdx.x * 128;
    const int bn = blockIdx.y * 128;

    float acc[4][4][4];
#pragma unroll
    for (int i = 0; i < 4; i++)
#pragma unroll
        for (int j = 0; j < 4; j++)
#pragma unroll
            for (int f = 0; f < 4; f++) acc[i][j][f] = 0.0f;

    for (int k0 = 0; k0 < K; k0 += 32) {
#pragma unroll
        for (int i = 0; i < 4; i++) {
            int v   = i * 256 + tid;
            int row = v >> 3;
            int col = (v & 7) * 4;
            float4 av = make_float4(0.f, 0.f, 0.f, 0.f);
            int gm = bm + row;
            if (gm < M)
                av = *(const float4*)(A + (size_t)gm * K + k0 + col);
            uint32_t* dst = &As[row * APAD + col];
            uint4 u;
            u.x = f32_to_tf32(av.x); u.y = f32_to_tf32(av.y);
            u.z = f32_to_tf32(av.z); u.w = f32_to_tf32(av.w);
            *(uint4*)dst = u;
        }
#pragma unroll
        for (int i = 0; i < 4; i++) {
            int v   = i * 256 + tid;
            int row = v >> 5;
            int col = (v & 31) * 4;
            float4 bv = *(const float4*)(B + (size_t)(k0 + row) * N + bn + col);
            uint32_t* dst = &Bs[row * BPAD + col];
            uint4 u;
            u.x = f32_to_tf32(bv.x); u.y = f32_to_tf32(bv.y);
            u.z = f32_to_tf32(bv.z); u.w = f32_to_tf32(bv.w);
            *(uint4*)dst = u;
        }
        __syncthreads();

#pragma unroll
        for (int ks = 0; ks < 4; ks++) {
            const int kk = ks * 8;
            uint32_t a[4][4], b[4][2];
#pragma unroll
            for (int mt = 0; mt < 4; mt++) {
                int r = wm + mt * 16 + gid;
                a[mt][0] = As[(r    ) * APAD + kk + tig    ];
                a[mt][1] = As[(r + 8) * APAD + kk + tig    ];
                a[mt][2] = As[(r    ) * APAD + kk + tig + 4];
                a[mt][3] = As[(r + 8) * APAD + kk + tig + 4];
            }
#pragma unroll
            for (int nt = 0; nt < 4; nt++) {
                int n = wn + nt * 8 + gid;
                b[nt][0] = Bs[(kk + tig    ) * BPAD + n];
                b[nt][1] = Bs[(kk + tig + 4) * BPAD + n];
            }
#pragma unroll
            for (int mt = 0; mt < 4; mt++)
#pragma unroll
                for (int nt = 0; nt < 4; nt++)
                    mma_tf32(acc[mt][nt], a[mt], b[nt]);
        }
        __syncthreads();
    }

#pragma unroll
    for (int mt = 0; mt < 4; mt++) {
        int r0 = bm + wm + mt * 16 + gid;
        int r1 = r0 + 8;
#pragma unroll
        for (int nt = 0; nt < 4; nt++) {
            int cc = bn + wn + nt * 8 + tig * 2;
            if (r0 < M) {
                float2 v0;
                v0.x = fmaxf(acc[mt][nt][0], 0.0f);
                v0.y = fmaxf(acc[mt][nt][1], 0.0f);
                *(float2*)(C + (size_t)r0 * N + cc) = v0;
            }
            if (r1 < M) {
                float2 v1;
                v1.x = fmaxf(acc[mt][nt][2], 0.0f);
                v1.y = fmaxf(acc[mt][nt][3], 0.0f);
                *(float2*)(C + (size_t)r1 * N + cc) = v1;
            }
        }
    }
}

// ---------------------------------------------------------------------------
// Launch
// ---------------------------------------------------------------------------
extern "C" void kernel_launch(void* const* d_in, const int* in_sizes, int n_in,
                              void* d_out, int out_size) {
    const float* x = nullptr;
    const float* W0 = nullptr;
    const float* W1 = nullptr;
    const void*  ei = nullptr;
    for (int i = 0; i < n_in; i++) {
        switch (in_sizes[i]) {
            case NNODES * NIN:   x  = (const float*)d_in[i]; break; // 6,400,000
            case NIN * NHID:     W0 = (const float*)d_in[i]; break; //    32,768
            case NHID * NHID:    W1 = (const float*)d_in[i]; break; //    65,536
            case 2 * NEDGES:     ei = d_in[i];               break; // 1,600,000
        }
    }

    float* out = (float*)d_out;

    float* agg; cudaGetSymbolAddress((void**)&agg, g_agg4);
    float* h1;  cudaGetSymbolAddress((void**)&h1,  g_h1);

    const int NBe = (NEDGES + 255) / 256;

    // Prolog: 5 launches (was 8)
    zero_detect_kernel<<<NB_SCAN, 256>>>((const int*)ei);
    convert_idx_kernel<<<NBe, 256>>>(ei);
    scan1_dinv_kernel<<<NB_SCAN, 256>>>();
    scan23_kernel<<<NB_SCAN, 256>>>();
    fill_csr_kernel<<<NBe, 256>>>();

    // Phase 2: CSR gather (one warp per node), self-loop fused
    {
        int blocks = (NNODES * 32 + 255) / 256;
        gather_kernel<<<blocks, 256>>>((const float4*)x);
    }

    // Phase 3: TF32 tensor-core GEMMs + ReLU (proven Round-4/5 kernel)
    {
        dim3 grid1((NNODES + 127) / 128, NHID / 128);
        gemm_tf32_relu_kernel<<<grid1, 256>>>(agg, W0, h1, NNODES, NIN, NHID);
        dim3 grid2((NNODES + 127) / 128, NHID / 128);
        gemm_tf32_relu_kernel<<<grid2, 256>>>(h1, W1, out, NNODES, NHID, NHID);
    }
}

// round 9
// speedup vs baseline: 2.7623x; 1.1712x over previous
#include <cuda_runtime.h>
#include <cuda_fp16.h>
#include <cstdint>

// Problem constants (fixed by the reference)
#define NNODES 50000
#define NEDGES 800000
#define NIN    128
#define NHID   256
#define NB_SCAN ((NNODES + 255) / 256)   // 196

// Scratch (allocation-free rule: __device__ globals)
__device__ float  g_dinv[NNODES];
__device__ int    g_row [NEDGES];
__device__ int    g_col [NEDGES];
__device__ int    g_cnt [NNODES];
__device__ int    g_ptr [NNODES];
__device__ int    g_cur [NNODES];
__device__ int    g_bsum[NB_SCAN];
__device__ int    g_esrc[NEDGES];
__device__ int    g_is64;
__device__ __align__(16) __half g_xh  [NNODES * NIN];    // 12.8 MB  x in half
__device__ __align__(16) __half g_aggh[NNODES * NIN];    // 12.8 MB  aggregated, half
__device__ __align__(16) __half g_h1h [NNODES * NHID];   // 25.6 MB  layer-1 out, half
__device__ __align__(16) __half g_w0t [NHID * NIN];      // W0^T [n][k] half
__device__ __align__(16) __half g_w1t [NHID * NHID];     // W1^T [n][k] half

// ---------------------------------------------------------------------------
// Fused: zero histogram + dtype detection (block 0 detects int32 vs int64).
// ---------------------------------------------------------------------------
__global__ void zero_detect_kernel(const int* __restrict__ ei32) {
    int i = blockIdx.x * 256 + threadIdx.x;
    if (i < NNODES) g_cnt[i] = 0;
    if (blockIdx.x == 0) {
        __shared__ int bad;
        if (threadIdx.x == 0) bad = 0;
        __syncthreads();
        for (int k = threadIdx.x; k < 4096; k += 256) {
            int hi = ei32[2 * k + 1];
            int lo = ei32[2 * k];
            if (hi != 0 || (unsigned)lo >= (unsigned)NNODES) bad = 1;
        }
        __syncthreads();
        if (threadIdx.x == 0) g_is64 = bad ? 0 : 1;
    }
}

// Convert indices to int32 AND histogram destinations.
__global__ void convert_idx_kernel(const void* __restrict__ ei) {
    int e = blockIdx.x * blockDim.x + threadIdx.x;
    if (e >= NEDGES) return;
    int r, c;
    if (g_is64) {
        const long long* p = (const long long*)ei;
        r = (int)p[e];
        c = (int)p[NEDGES + e];
    } else {
        const int* p = (const int*)ei;
        r = p[e];
        c = p[NEDGES + e];
    }
    r = min(max(r, 0), NNODES - 1);   // defensive: rel_err, never IMA
    c = min(max(c, 0), NNODES - 1);
    g_row[e] = r;
    g_col[e] = c;
    atomicAdd(&g_cnt[c], 1);
}

// x (fp32) -> half copy, 8 elems/thread
__global__ void xhalf_kernel(const float4* __restrict__ x4) {
    int t = blockIdx.x * blockDim.x + threadIdx.x;
    if (t >= NNODES * NIN / 8) return;
    float4 a = x4[2 * t];
    float4 b = x4[2 * t + 1];
    __half2 h0 = __floats2half2_rn(a.x, a.y);
    __half2 h1 = __floats2half2_rn(a.z, a.w);
    __half2 h2 = __floats2half2_rn(b.x, b.y);
    __half2 h3 = __floats2half2_rn(b.z, b.w);
    uint4 u;
    u.x = *reinterpret_cast<uint32_t*>(&h0);
    u.y = *reinterpret_cast<uint32_t*>(&h1);
    u.z = *reinterpret_cast<uint32_t*>(&h2);
    u.w = *reinterpret_cast<uint32_t*>(&h3);
    ((uint4*)g_xh)[t] = u;
}

// W [K][N] fp32 -> Wt [N][K] half
__global__ void wtrans_kernel(const float* __restrict__ W, __half* __restrict__ Wt,
                              int K, int N) {
    int t = blockIdx.x * blockDim.x + threadIdx.x;
    if (t >= K * N) return;
    int k = t / N;
    int n = t - k * N;
    Wt[n * K + k] = __float2half(W[t]);
}

// ---------------------------------------------------------------------------
// Fused scan stage 1 + dinv.
// ---------------------------------------------------------------------------
__global__ void scan1_dinv_kernel() {
    __shared__ int sh[256];
    int i = blockIdx.x * 256 + threadIdx.x;
    int v = (i < NNODES) ? g_cnt[i] : 0;
    if (i < NNODES) g_dinv[i] = rsqrtf(1.0f + (float)v);
    sh[threadIdx.x] = v;
    __syncthreads();
#pragma unroll
    for (int off = 1; off < 256; off <<= 1) {
        int t = (threadIdx.x >= off) ? sh[threadIdx.x - off] : 0;
        __syncthreads();
        sh[threadIdx.x] += t;
        __syncthreads();
    }
    int incl = sh[threadIdx.x];
    if (i < NNODES) g_ptr[i] = incl - v;
    if (threadIdx.x == 255) g_bsum[blockIdx.x] = incl;
}

// Fused scan stages 2+3 (redundant per-block scan of block sums).
__global__ void scan23_kernel() {
    __shared__ int sh[256];
    __shared__ int excl;
    int t = threadIdx.x;
    int v = (t < NB_SCAN) ? g_bsum[t] : 0;
    sh[t] = v;
    __syncthreads();
#pragma unroll
    for (int off = 1; off < 256; off <<= 1) {
        int u = (t >= off) ? sh[t - off] : 0;
        __syncthreads();
        sh[t] += u;
        __syncthreads();
    }
    if (t == blockIdx.x) excl = sh[t] - v;
    __syncthreads();
    int i = blockIdx.x * 256 + t;
    if (i < NNODES) {
        int p = g_ptr[i] + excl;
        g_ptr[i] = p;
        g_cur[i] = p;
    }
}

__global__ void fill_csr_kernel() {
    int e = blockIdx.x * blockDim.x + threadIdx.x;
    if (e >= NEDGES) return;
    int c = g_col[e];
    int pos = atomicAdd(&g_cur[c], 1);
    g_esrc[pos] = g_row[e];
}

// ---------------------------------------------------------------------------
// Phase 2: CSR gather, fp16 neighbor reads, fp32 accumulate, half output.
// One warp per destination node; lane owns 4 features (8 bytes of half).
// out = dinv[i]*(dinv[i]*x[i] + sum dinv[j]*x_h[j])
// ---------------------------------------------------------------------------
__global__ __launch_bounds__(256)
void gather_kernel(const float4* __restrict__ x4) {
    int warp = (blockIdx.x * blockDim.x + threadIdx.x) >> 5;
    int lane = threadIdx.x & 31;
    if (warp >= NNODES) return;

    const int beg = g_ptr[warp];
    const int cnt = g_cnt[warp];
    const float di = g_dinv[warp];

    // self-loop term from full-precision x
    float4 acc = x4[(size_t)warp * 32 + lane];
    acc.x *= di; acc.y *= di; acc.z *= di; acc.w *= di;

    const uint2* xh2 = (const uint2*)g_xh;   // 4 halves per elem, 32 per row

    int base = 0;
    for (; base + 32 <= cnt; base += 32) {
        int   s = g_esrc[beg + base + lane];
        float w = g_dinv[s];
#pragma unroll
        for (int j = 0; j < 32; j++) {
            int   ss = __shfl_sync(0xffffffffu, s, j);
            float ww = __shfl_sync(0xffffffffu, w, j);
            uint2 u = xh2[(size_t)ss * 32 + lane];
            __half2 p0 = *reinterpret_cast<__half2*>(&u.x);
            __half2 p1 = *reinterpret_cast<__half2*>(&u.y);
            float2 f0 = __half22float2(p0);
            float2 f1 = __half22float2(p1);
            acc.x = fmaf(ww, f0.x, acc.x);
            acc.y = fmaf(ww, f0.y, acc.y);
            acc.z = fmaf(ww, f1.x, acc.z);
            acc.w = fmaf(ww, f1.y, acc.w);
        }
    }
    {
        int rem = cnt - base;
        int   s = 0; float w = 0.0f;
        if (lane < rem) {
            s = g_esrc[beg + base + lane];
            w = g_dinv[s];
        }
        for (int j = 0; j < rem; j++) {
            int   ss = __shfl_sync(0xffffffffu, s, j);
            float ww = __shfl_sync(0xffffffffu, w, j);
            uint2 u = xh2[(size_t)ss * 32 + lane];
            __half2 p0 = *reinterpret_cast<__half2*>(&u.x);
            __half2 p1 = *reinterpret_cast<__half2*>(&u.y);
            float2 f0 = __half22float2(p0);
            float2 f1 = __half22float2(p1);
            acc.x = fmaf(ww, f0.x, acc.x);
            acc.y = fmaf(ww, f0.y, acc.y);
            acc.z = fmaf(ww, f1.x, acc.z);
            acc.w = fmaf(ww, f1.y, acc.w);
        }
    }

    acc.x *= di; acc.y *= di; acc.z *= di; acc.w *= di;
    __half2 o0 = __floats2half2_rn(acc.x, acc.y);
    __half2 o1 = __floats2half2_rn(acc.z, acc.w);
    uint2 o;
    o.x = *reinterpret_cast<uint32_t*>(&o0);
    o.y = *reinterpret_cast<uint32_t*>(&o1);
    ((uint2*)g_aggh)[(size_t)warp * 32 + lane] = o;
}

// ---------------------------------------------------------------------------
// Phase 3: FP16 tensor-core GEMM + ReLU.  C[M,N] = relu(A[M,K] @ Bt[N,K]^T).
// A half [M][K] row-major; Bt half [N][K] (pre-transposed weights).
// 128x128 tile, BK=32, 256 threads (2x4 warps), warp tile 64x32,
// mma.sync.aligned.m16n8k16.row.col.f32.f16.f16.f32.
// HALF_OUT: store half (for h1), else float (final output).
// ---------------------------------------------------------------------------
__device__ __forceinline__ void mma_f16(float* c, const uint32_t* a,
                                        const uint32_t* b) {
    asm volatile(
        "mma.sync.aligned.m16n8k16.row.col.f32.f16.f16.f32 "
        "{%0,%1,%2,%3}, {%4,%5,%6,%7}, {%8,%9}, {%0,%1,%2,%3};"
        : "+f"(c[0]), "+f"(c[1]), "+f"(c[2]), "+f"(c[3])
        : "r"(a[0]), "r"(a[1]), "r"(a[2]), "r"(a[3]), "r"(b[0]), "r"(b[1]));
}

// HPAD=40 halves/row (20 half2): frag bank = gid*20 mod 32 in
// {0,20,8,28,16,4,24,12} + tig{0..3} -> 32 distinct banks. Same for A and B.
#define HPAD 40

template <bool HALF_OUT>
__global__ __launch_bounds__(256, 2)
void gemm_f16_relu_kernel(const __half* __restrict__ A,
                          const __half* __restrict__ Bt,
                          void* __restrict__ Cv, int M, int K, int N) {
    __shared__ __half As[128 * HPAD];
    __shared__ __half Bs[128 * HPAD];

    const int tid  = threadIdx.x;
    const int lane = tid & 31;
    const int wid  = tid >> 5;
    const int wm   = (wid & 1) * 64;
    const int wn   = (wid >> 1) * 32;
    const int gid  = lane >> 2;
    const int tig  = lane & 3;

    const int bm = blockIdx.x * 128;
    const int bn = blockIdx.y * 128;

    float acc[4][4][4];
#pragma unroll
    for (int i = 0; i < 4; i++)
#pragma unroll
        for (int j = 0; j < 4; j++)
#pragma unroll
            for (int f = 0; f < 4; f++) acc[i][j][f] = 0.0f;

    for (int k0 = 0; k0 < K; k0 += 32) {
        // A tile: 128 rows x 32 halves = 512 uint4 chunks
#pragma unroll
        for (int i = 0; i < 2; i++) {
            int v   = i * 256 + tid;
            int row = v >> 2;
            int ch  = v & 3;
            int gm  = min(bm + row, M - 1);   // clamped rows never stored
            uint4 u = *(const uint4*)(A + (size_t)gm * K + k0 + ch * 8);
            *(uint4*)&As[row * HPAD + ch * 8] = u;
        }
        // B tile: 128 n-rows x 32 halves from Bt[N][K]
#pragma unroll
        for (int i = 0; i < 2; i++) {
            int v   = i * 256 + tid;
            int row = v >> 2;
            int ch  = v & 3;
            uint4 u = *(const uint4*)(Bt + (size_t)(bn + row) * K + k0 + ch * 8);
            *(uint4*)&Bs[row * HPAD + ch * 8] = u;
        }
        __syncthreads();

        const uint32_t* As2 = (const uint32_t*)As;   // half2 units, stride 20
        const uint32_t* Bs2 = (const uint32_t*)Bs;

#pragma unroll
        for (int ks = 0; ks < 2; ks++) {
            const int kb = ks * 8;   // half2 offset within row
            uint32_t a[4][4], b[4][2];
#pragma unroll
            for (int mt = 0; mt < 4; mt++) {
                int r = wm + mt * 16 + gid;
                a[mt][0] = As2[(r    ) * 20 + kb + tig    ];
                a[mt][1] = As2[(r + 8) * 20 + kb + tig    ];
                a[mt][2] = As2[(r    ) * 20 + kb + tig + 4];
                a[mt][3] = As2[(r + 8) * 20 + kb + tig + 4];
            }
#pragma unroll
            for (int nt = 0; nt < 4; nt++) {
                int n = wn + nt * 8 + gid;
                b[nt][0] = Bs2[n * 20 + kb + tig    ];
                b[nt][1] = Bs2[n * 20 + kb + tig + 4];
            }
#pragma unroll
            for (int mt = 0; mt < 4; mt++)
#pragma unroll
                for (int nt = 0; nt < 4; nt++)
                    mma_f16(acc[mt][nt], a[mt], b[nt]);
        }
        __syncthreads();
    }

    // ---- epilogue: ReLU + store ----
#pragma unroll
    for (int mt = 0; mt < 4; mt++) {
        int r0 = bm + wm + mt * 16 + gid;
        int r1 = r0 + 8;
#pragma unroll
        for (int nt = 0; nt < 4; nt++) {
            int cc = bn + wn + nt * 8 + tig * 2;
            float v00 = fmaxf(acc[mt][nt][0], 0.0f);
            float v01 = fmaxf(acc[mt][nt][1], 0.0f);
            float v10 = fmaxf(acc[mt][nt][2], 0.0f);
            float v11 = fmaxf(acc[mt][nt][3], 0.0f);
            if (HALF_OUT) {
                __half* C = (__half*)Cv;
                if (r0 < M) {
                    __half2 h = __floats2half2_rn(v00, v01);
                    *(uint32_t*)(C + (size_t)r0 * N + cc) =
                        *reinterpret_cast<uint32_t*>(&h);
                }
                if (r1 < M) {
                    __half2 h = __floats2half2_rn(v10, v11);
                    *(uint32_t*)(C + (size_t)r1 * N + cc) =
                        *reinterpret_cast<uint32_t*>(&h);
                }
            } else {
                float* C = (float*)Cv;
                if (r0 < M) {
                    float2 f = make_float2(v00, v01);
                    *(float2*)(C + (size_t)r0 * N + cc) = f;
                }
                if (r1 < M) {
                    float2 f = make_float2(v10, v11);
                    *(float2*)(C + (size_t)r1 * N + cc) = f;
                }
            }
        }
    }
}

// ---------------------------------------------------------------------------
// Launch
// ---------------------------------------------------------------------------
extern "C" void kernel_launch(void* const* d_in, const int* in_sizes, int n_in,
                              void* d_out, int out_size) {
    const float* x = nullptr;
    const float* W0 = nullptr;
    const float* W1 = nullptr;
    const void*  ei = nullptr;
    for (int i = 0; i < n_in; i++) {
        switch (in_sizes[i]) {
            case NNODES * NIN:   x  = (const float*)d_in[i]; break; // 6,400,000
            case NIN * NHID:     W0 = (const float*)d_in[i]; break; //    32,768
            case NHID * NHID:    W1 = (const float*)d_in[i]; break; //    65,536
            case 2 * NEDGES:     ei = d_in[i];               break; // 1,600,000
        }
    }

    float* out = (float*)d_out;

    __half* aggh; cudaGetSymbolAddress((void**)&aggh, g_aggh);
    __half* h1h;  cudaGetSymbolAddress((void**)&h1h,  g_h1h);
    __half* w0t;  cudaGetSymbolAddress((void**)&w0t,  g_w0t);
    __half* w1t;  cudaGetSymbolAddress((void**)&w1t,  g_w1t);

    const int NBe = (NEDGES + 255) / 256;

    // Prolog: dtype detect + histogram + precision conversions + CSR build
    zero_detect_kernel<<<NB_SCAN, 256>>>((const int*)ei);
    xhalf_kernel<<<(NNODES * NIN / 8 + 255) / 256, 256>>>((const float4*)x);
    wtrans_kernel<<<(NIN * NHID + 255) / 256, 256>>>(W0, w0t, NIN, NHID);
    wtrans_kernel<<<(NHID * NHID + 255) / 256, 256>>>(W1, w1t, NHID, NHID);
    convert_idx_kernel<<<NBe, 256>>>(ei);
    scan1_dinv_kernel<<<NB_SCAN, 256>>>();
    scan23_kernel<<<NB_SCAN, 256>>>();
    fill_csr_kernel<<<NBe, 256>>>();

    // Phase 2: CSR gather (one warp per node), fp16 reads, half output
    {
        int blocks = (NNODES * 32 + 255) / 256;
        gather_kernel<<<blocks, 256>>>((const float4*)x);
    }

    // Phase 3: FP16 tensor-core GEMMs + ReLU
    {
        dim3 grid((NNODES + 127) / 128, NHID / 128);
        gemm_f16_relu_kernel<true ><<<grid, 256>>>(aggh, w0t, h1h,
                                                   NNODES, NIN, NHID);
        gemm_f16_relu_kernel<false><<<grid, 256>>>(h1h, w1t, out,
                                                   NNODES, NHID, NHID);
    }
}

// round 10
// speedup vs baseline: 2.8398x; 1.0281x over previous
#include <cuda_runtime.h>
#include <cuda_fp16.h>
#include <cstdint>

// Problem constants (fixed by the reference)
#define NNODES 50000
#define NEDGES 800000
#define NIN    128
#define NHID   256
#define NB_SCAN ((NNODES + 255) / 256)   // 196

// Scratch (allocation-free rule: __device__ globals)
__device__ float  g_dinv[NNODES];
__device__ int    g_cnt [NNODES];
__device__ int    g_ptr [NNODES];
__device__ int    g_cur [NNODES];
__device__ int    g_bsum[NB_SCAN];
__device__ int    g_esrc[NEDGES];
__device__ int    g_is64;
__device__ __align__(16) __half g_xh  [NNODES * NIN];    // 12.8 MB
__device__ __align__(16) __half g_aggh[NNODES * NIN];    // 12.8 MB
__device__ __align__(16) __half g_h1h [NNODES * NHID];   // 25.6 MB
__device__ __align__(16) __half g_w0t [NHID * NIN];      // W0^T [n][k]
__device__ __align__(16) __half g_w1t [NHID * NHID];     // W1^T [n][k]

// ---------------------------------------------------------------------------
// Fused: zero histogram + dtype detection (block 0).
// ---------------------------------------------------------------------------
__global__ void zero_detect_kernel(const int* __restrict__ ei32) {
    int i = blockIdx.x * 256 + threadIdx.x;
    if (i < NNODES) g_cnt[i] = 0;
    if (blockIdx.x == 0) {
        __shared__ int bad;
        if (threadIdx.x == 0) bad = 0;
        __syncthreads();
        for (int k = threadIdx.x; k < 4096; k += 256) {
            int hi = ei32[2 * k + 1];
            int lo = ei32[2 * k];
            if (hi != 0 || (unsigned)lo >= (unsigned)NNODES) bad = 1;
        }
        __syncthreads();
        if (threadIdx.x == 0) g_is64 = bad ? 0 : 1;
    }
}

__device__ __forceinline__ int load_dst(const void* ei, int e) {
    int c = g_is64 ? (int)((const long long*)ei)[NEDGES + e]
                   : ((const int*)ei)[NEDGES + e];
    return min(max(c, 0), NNODES - 1);
}
__device__ __forceinline__ int load_src(const void* ei, int e) {
    int r = g_is64 ? (int)((const long long*)ei)[e]
                   : ((const int*)ei)[e];
    return min(max(r, 0), NNODES - 1);
}

// Histogram destinations (no index materialization).
__global__ void hist_kernel(const void* __restrict__ ei) {
    int e = blockIdx.x * blockDim.x + threadIdx.x;
    if (e >= NEDGES) return;
    atomicAdd(&g_cnt[load_dst(ei, e)], 1);
}

// x (fp32) -> half, 8 elems/thread
__global__ void xhalf_kernel(const float4* __restrict__ x4) {
    int t = blockIdx.x * blockDim.x + threadIdx.x;
    if (t >= NNODES * NIN / 8) return;
    float4 a = x4[2 * t];
    float4 b = x4[2 * t + 1];
    __half2 h0 = __floats2half2_rn(a.x, a.y);
    __half2 h1 = __floats2half2_rn(a.z, a.w);
    __half2 h2 = __floats2half2_rn(b.x, b.y);
    __half2 h3 = __floats2half2_rn(b.z, b.w);
    uint4 u;
    u.x = *reinterpret_cast<uint32_t*>(&h0);
    u.y = *reinterpret_cast<uint32_t*>(&h1);
    u.z = *reinterpret_cast<uint32_t*>(&h2);
    u.w = *reinterpret_cast<uint32_t*>(&h3);
    ((uint4*)g_xh)[t] = u;
}

// W [K][N] fp32 -> Wt [N][K] half
__global__ void wtrans_kernel(const float* __restrict__ W, __half* __restrict__ Wt,
                              int K, int N) {
    int t = blockIdx.x * blockDim.x + threadIdx.x;
    if (t >= K * N) return;
    int k = t / N;
    int n = t - k * N;
    Wt[n * K + k] = __float2half(W[t]);
}

// ---------------------------------------------------------------------------
// Scan stage 1 + dinv.
// ---------------------------------------------------------------------------
__global__ void scan1_dinv_kernel() {
    __shared__ int sh[256];
    int i = blockIdx.x * 256 + threadIdx.x;
    int v = (i < NNODES) ? g_cnt[i] : 0;
    if (i < NNODES) g_dinv[i] = rsqrtf(1.0f + (float)v);
    sh[threadIdx.x] = v;
    __syncthreads();
#pragma unroll
    for (int off = 1; off < 256; off <<= 1) {
        int t = (threadIdx.x >= off) ? sh[threadIdx.x - off] : 0;
        __syncthreads();
        sh[threadIdx.x] += t;
        __syncthreads();
    }
    int incl = sh[threadIdx.x];
    if (i < NNODES) g_ptr[i] = incl - v;
    if (threadIdx.x == 255) g_bsum[blockIdx.x] = incl;
}

// Scan stages 2+3 (redundant per-block scan of block sums).
__global__ void scan23_kernel() {
    __shared__ int sh[256];
    __shared__ int excl;
    int t = threadIdx.x;
    int v = (t < NB_SCAN) ? g_bsum[t] : 0;
    sh[t] = v;
    __syncthreads();
#pragma unroll
    for (int off = 1; off < 256; off <<= 1) {
        int u = (t >= off) ? sh[t - off] : 0;
        __syncthreads();
        sh[t] += u;
        __syncthreads();
    }
    if (t == blockIdx.x) excl = sh[t] - v;
    __syncthreads();
    int i = blockIdx.x * 256 + t;
    if (i < NNODES) {
        int p = g_ptr[i] + excl;
        g_ptr[i] = p;
        g_cur[i] = p;
    }
}

// Fill CSR directly from ei (no intermediate row/col arrays).
__global__ void fill_csr_kernel(const void* __restrict__ ei) {
    int e = blockIdx.x * blockDim.x + threadIdx.x;
    if (e >= NEDGES) return;
    int c = load_dst(ei, e);
    int r = load_src(ei, e);
    int pos = atomicAdd(&g_cur[c], 1);
    g_esrc[pos] = r;
}

// ---------------------------------------------------------------------------
// Phase 2: CSR gather, fp16 neighbor reads, fp32 accumulate, half output.
// ---------------------------------------------------------------------------
__global__ __launch_bounds__(256)
void gather_kernel(const float4* __restrict__ x4) {
    int warp = (blockIdx.x * blockDim.x + threadIdx.x) >> 5;
    int lane = threadIdx.x & 31;
    if (warp >= NNODES) return;

    const int beg = g_ptr[warp];
    const int cnt = g_cnt[warp];
    const float di = g_dinv[warp];

    float4 acc = x4[(size_t)warp * 32 + lane];
    acc.x *= di; acc.y *= di; acc.z *= di; acc.w *= di;

    const uint2* xh2 = (const uint2*)g_xh;

    int base = 0;
    for (; base + 32 <= cnt; base += 32) {
        int   s = g_esrc[beg + base + lane];
        float w = g_dinv[s];
#pragma unroll
        for (int j = 0; j < 32; j++) {
            int   ss = __shfl_sync(0xffffffffu, s, j);
            float ww = __shfl_sync(0xffffffffu, w, j);
            uint2 u = xh2[(size_t)ss * 32 + lane];
            __half2 p0 = *reinterpret_cast<__half2*>(&u.x);
            __half2 p1 = *reinterpret_cast<__half2*>(&u.y);
            float2 f0 = __half22float2(p0);
            float2 f1 = __half22float2(p1);
            acc.x = fmaf(ww, f0.x, acc.x);
            acc.y = fmaf(ww, f0.y, acc.y);
            acc.z = fmaf(ww, f1.x, acc.z);
            acc.w = fmaf(ww, f1.y, acc.w);
        }
    }
    {
        int rem = cnt - base;
        int   s = 0; float w = 0.0f;
        if (lane < rem) {
            s = g_esrc[beg + base + lane];
            w = g_dinv[s];
        }
        for (int j = 0; j < rem; j++) {
            int   ss = __shfl_sync(0xffffffffu, s, j);
            float ww = __shfl_sync(0xffffffffu, w, j);
            uint2 u = xh2[(size_t)ss * 32 + lane];
            __half2 p0 = *reinterpret_cast<__half2*>(&u.x);
            __half2 p1 = *reinterpret_cast<__half2*>(&u.y);
            float2 f0 = __half22float2(p0);
            float2 f1 = __half22float2(p1);
            acc.x = fmaf(ww, f0.x, acc.x);
            acc.y = fmaf(ww, f0.y, acc.y);
            acc.z = fmaf(ww, f1.x, acc.z);
            acc.w = fmaf(ww, f1.y, acc.w);
        }
    }

    acc.x *= di; acc.y *= di; acc.z *= di; acc.w *= di;
    __half2 o0 = __floats2half2_rn(acc.x, acc.y);
    __half2 o1 = __floats2half2_rn(acc.z, acc.w);
    uint2 o;
    o.x = *reinterpret_cast<uint32_t*>(&o0);
    o.y = *reinterpret_cast<uint32_t*>(&o1);
    ((uint2*)g_aggh)[(size_t)warp * 32 + lane] = o;
}

// ---------------------------------------------------------------------------
// Phase 3: FP16 tensor-core GEMM + ReLU with ldmatrix fragment loads.
// C[M,N] = relu(A[M,K] @ Bt[N,K]^T); 128x128 tile, BK=32, 2x4 warps,
// warp tile 64x32, mma.sync.m16n8k16.f32.f16.f16.f32.
// ---------------------------------------------------------------------------
__device__ __forceinline__ void mma_f16(float* c, const uint32_t* a,
                                        const uint32_t* b) {
    asm volatile(
        "mma.sync.aligned.m16n8k16.row.col.f32.f16.f16.f32 "
        "{%0,%1,%2,%3}, {%4,%5,%6,%7}, {%8,%9}, {%0,%1,%2,%3};"
        : "+f"(c[0]), "+f"(c[1]), "+f"(c[2]), "+f"(c[3])
        : "r"(a[0]), "r"(a[1]), "r"(a[2]), "r"(a[3]), "r"(b[0]), "r"(b[1]));
}

__device__ __forceinline__ void ldsm_x4(uint32_t* r, uint32_t saddr) {
    asm volatile("ldmatrix.sync.aligned.m8n8.x4.shared.b16 {%0,%1,%2,%3}, [%4];"
                 : "=r"(r[0]), "=r"(r[1]), "=r"(r[2]), "=r"(r[3]) : "r"(saddr));
}
__device__ __forceinline__ void ldsm_x2(uint32_t* r, uint32_t saddr) {
    asm volatile("ldmatrix.sync.aligned.m8n8.x2.shared.b16 {%0,%1}, [%2];"
                 : "=r"(r[0]), "=r"(r[1]) : "r"(saddr));
}

// HPAD=40 halves/row (80B): ldmatrix row addresses land on bank groups
// 20*r mod 32 in {0,20,8,28,16,4,24,12}; each 16B row covers 4 banks
// -> 8 rows cover all 32 banks, conflict-free.
#define HPAD 40

template <bool HALF_OUT>
__global__ __launch_bounds__(256, 2)
void gemm_f16_relu_kernel(const __half* __restrict__ A,
                          const __half* __restrict__ Bt,
                          void* __restrict__ Cv, int M, int K, int N) {
    __shared__ __half As[128 * HPAD];
    __shared__ __half Bs[128 * HPAD];

    const int tid  = threadIdx.x;
    const int lane = tid & 31;
    const int wid  = tid >> 5;
    const int wm   = (wid & 1) * 64;
    const int wn   = (wid >> 1) * 32;
    const int gid  = lane >> 2;
    const int tig  = lane & 3;

    const int bm = blockIdx.x * 128;
    const int bn = blockIdx.y * 128;

    const uint32_t as_base = (uint32_t)__cvta_generic_to_shared(As);
    const uint32_t bs_base = (uint32_t)__cvta_generic_to_shared(Bs);

    // ldmatrix per-lane row/k-offset selectors (in halves)
    const int a_row_sel = lane & 15;           // row within 16-row tile
    const int a_kh_sel  = (lane >> 4) * 8;     // 0 or 8 halves
    const int b_row_sel = lane & 7;            // row within 8-n tile
    const int b_kh_sel  = ((lane >> 3) & 1) * 8;

    float acc[4][4][4];
#pragma unroll
    for (int i = 0; i < 4; i++)
#pragma unroll
        for (int j = 0; j < 4; j++)
#pragma unroll
            for (int f = 0; f < 4; f++) acc[i][j][f] = 0.0f;

    for (int k0 = 0; k0 < K; k0 += 32) {
        // A tile: 128 rows x 32 halves = 512 uint4 chunks
#pragma unroll
        for (int i = 0; i < 2; i++) {
            int v   = i * 256 + tid;
            int row = v >> 2;
            int ch  = v & 3;
            int gm  = min(bm + row, M - 1);   // clamped rows never stored
            uint4 u = *(const uint4*)(A + (size_t)gm * K + k0 + ch * 8);
            *(uint4*)&As[row * HPAD + ch * 8] = u;
        }
        // B tile: 128 n-rows x 32 halves from Bt[N][K]
#pragma unroll
        for (int i = 0; i < 2; i++) {
            int v   = i * 256 + tid;
            int row = v >> 2;
            int ch  = v & 3;
            uint4 u = *(const uint4*)(Bt + (size_t)(bn + row) * K + k0 + ch * 8);
            *(uint4*)&Bs[row * HPAD + ch * 8] = u;
        }
        __syncthreads();

#pragma unroll
        for (int ks = 0; ks < 2; ks++) {
            const int kh = ks * 16;   // half offset within BK=32 row
            uint32_t a[4][4], b[4][2];
#pragma unroll
            for (int mt = 0; mt < 4; mt++) {
                uint32_t addr = as_base +
                    (uint32_t)((wm + mt * 16 + a_row_sel) * HPAD + kh + a_kh_sel) * 2;
                ldsm_x4(a[mt], addr);
            }
#pragma unroll
            for (int nt = 0; nt < 4; nt++) {
                uint32_t addr = bs_base +
                    (uint32_t)((wn + nt * 8 + b_row_sel) * HPAD + kh + b_kh_sel) * 2;
                ldsm_x2(b[nt], addr);
            }
#pragma unroll
            for (int mt = 0; mt < 4; mt++)
#pragma unroll
                for (int nt = 0; nt < 4; nt++)
                    mma_f16(acc[mt][nt], a[mt], b[nt]);
        }
        __syncthreads();
    }

    // ---- epilogue: ReLU + store ----
#pragma unroll
    for (int mt = 0; mt < 4; mt++) {
        int r0 = bm + wm + mt * 16 + gid;
        int r1 = r0 + 8;
#pragma unroll
        for (int nt = 0; nt < 4; nt++) {
            int cc = bn + wn + nt * 8 + tig * 2;
            float v00 = fmaxf(acc[mt][nt][0], 0.0f);
            float v01 = fmaxf(acc[mt][nt][1], 0.0f);
            float v10 = fmaxf(acc[mt][nt][2], 0.0f);
            float v11 = fmaxf(acc[mt][nt][3], 0.0f);
            if (HALF_OUT) {
                __half* C = (__half*)Cv;
                if (r0 < M) {
                    __half2 h = __floats2half2_rn(v00, v01);
                    *(uint32_t*)(C + (size_t)r0 * N + cc) =
                        *reinterpret_cast<uint32_t*>(&h);
                }
                if (r1 < M) {
                    __half2 h = __floats2half2_rn(v10, v11);
                    *(uint32_t*)(C + (size_t)r1 * N + cc) =
                        *reinterpret_cast<uint32_t*>(&h);
                }
            } else {
                float* C = (float*)Cv;
                if (r0 < M) {
                    *(float2*)(C + (size_t)r0 * N + cc) = make_float2(v00, v01);
                }
                if (r1 < M) {
                    *(float2*)(C + (size_t)r1 * N + cc) = make_float2(v10, v11);
                }
            }
        }
    }
}

// ---------------------------------------------------------------------------
// Launch
// ---------------------------------------------------------------------------
extern "C" void kernel_launch(void* const* d_in, const int* in_sizes, int n_in,
                              void* d_out, int out_size) {
    const float* x = nullptr;
    const float* W0 = nullptr;
    const float* W1 = nullptr;
    const void*  ei = nullptr;
    for (int i = 0; i < n_in; i++) {
        switch (in_sizes[i]) {
            case NNODES * NIN:   x  = (const float*)d_in[i]; break; // 6,400,000
            case NIN * NHID:     W0 = (const float*)d_in[i]; break; //    32,768
            case NHID * NHID:    W1 = (const float*)d_in[i]; break; //    65,536
            case 2 * NEDGES:     ei = d_in[i];               break; // 1,600,000
        }
    }

    float* out = (float*)d_out;

    __half* aggh; cudaGetSymbolAddress((void**)&aggh, g_aggh);
    __half* h1h;  cudaGetSymbolAddress((void**)&h1h,  g_h1h);
    __half* w0t;  cudaGetSymbolAddress((void**)&w0t,  g_w0t);
    __half* w1t;  cudaGetSymbolAddress((void**)&w1t,  g_w1t);

    const int NBe = (NEDGES + 255) / 256;

    // Prolog
    zero_detect_kernel<<<NB_SCAN, 256>>>((const int*)ei);
    xhalf_kernel<<<(NNODES * NIN / 8 + 255) / 256, 256>>>((const float4*)x);
    wtrans_kernel<<<(NIN * NHID + 255) / 256, 256>>>(W0, w0t, NIN, NHID);
    wtrans_kernel<<<(NHID * NHID + 255) / 256, 256>>>(W1, w1t, NHID, NHID);
    hist_kernel<<<NBe, 256>>>(ei);
    scan1_dinv_kernel<<<NB_SCAN, 256>>>();
    scan23_kernel<<<NB_SCAN, 256>>>();
    fill_csr_kernel<<<NBe, 256>>>(ei);

    // Phase 2: CSR gather
    {
        int blocks = (NNODES * 32 + 255) / 256;
        gather_kernel<<<blocks, 256>>>((const float4*)x);
    }

    // Phase 3: FP16 tensor-core GEMMs + ReLU (ldmatrix fragments)
    {
        dim3 grid((NNODES + 127) / 128, NHID / 128);
        gemm_f16_relu_kernel<true ><<<grid, 256>>>(aggh, w0t, h1h,
                                                   NNODES, NIN, NHID);
        gemm_f16_relu_kernel<false><<<grid, 256>>>(h1h, w1t, out,
                                                   NNODES, NHID, NHID);
    }
}